// round 2
// baseline (speedup 1.0000x reference)
#include <cuda_runtime.h>

#define NT 4096      // total tokens
#define NH 16        // query heads
#define NG 4         // kv groups
#define HD 128       // head dim
#define NS 8         // num sequences
#define BQ 64        // queries per block (32 warps x 2 rows)
#define BK 32        // keys per smem tile

__device__ __forceinline__ float warp_sum(float v) {
    v += __shfl_xor_sync(0xffffffffu, v, 16);
    v += __shfl_xor_sync(0xffffffffu, v, 8);
    v += __shfl_xor_sync(0xffffffffu, v, 4);
    v += __shfl_xor_sync(0xffffffffu, v, 2);
    v += __shfl_xor_sync(0xffffffffu, v, 1);
    return v;
}

__global__ __launch_bounds__(1024, 1)
void attn_fwd(const float* __restrict__ Q, const float* __restrict__ K,
              const float* __restrict__ V, const int* __restrict__ CU,
              float* __restrict__ O)
{
    __shared__ float sK[BK][HD];
    __shared__ float sV[BK][HD];
    __shared__ int scu[NS + 1];

    const int tid  = threadIdx.x;
    const int warp = tid >> 5;
    const int lane = tid & 31;
    const int h = blockIdx.y;
    const int g = h >> 2;                 // GQA: 4 query heads per kv group
    const int q_base = blockIdx.x * BQ;
    const int q0 = q_base + warp * 2;
    const int q1 = q0 + 1;

    if (tid <= NS) scu[tid] = CU[tid];
    __syncthreads();

    // segment starts (last cu entry <= pos)
    int kbeg0 = 0, kbeg1 = 0, blk_beg = 0;
    #pragma unroll
    for (int s = 0; s <= NS; s++) {
        int c = scu[s];
        if (c <= q0)     kbeg0   = c;
        if (c <= q1)     kbeg1   = c;
        if (c <= q_base) blk_beg = c;
    }

    const float scale = 0.08838834764831845f; // 1/sqrt(128)
    float4 qa = *(const float4*)&Q[((size_t)q0 * NH + h) * HD + lane * 4];
    float4 qb = *(const float4*)&Q[((size_t)q1 * NH + h) * HD + lane * 4];
    qa.x *= scale; qa.y *= scale; qa.z *= scale; qa.w *= scale;
    qb.x *= scale; qb.y *= scale; qb.z *= scale; qb.w *= scale;

    float m0 = -1e30f, l0 = 0.f;
    float m1 = -1e30f, l1 = 0.f;
    float4 o0 = {0.f, 0.f, 0.f, 0.f};
    float4 o1 = {0.f, 0.f, 0.f, 0.f};

    const int kv_hi = q_base + BQ - 1;
    for (int kb = blk_beg; kb <= kv_hi; kb += BK) {
        __syncthreads();
        // Cooperative tile load: BK*HD/4 = 1024 float4 per tensor, one per thread
        {
            int r = tid >> 5;               // 0..31
            int c = (tid & 31) << 2;        // 0,4,...,124
            int krow = kb + r;
            if (krow < NT) {
                size_t base = ((size_t)krow * NG + g) * HD + c;
                *(float4*)&sK[r][c] = *(const float4*)&K[base];
                *(float4*)&sV[r][c] = *(const float4*)&V[base];
            }
        }
        __syncthreads();

        int lo = max(kb, min(kbeg0, kbeg1));
        int hi = min(kb + BK - 1, q1);
        for (int kk = lo; kk <= hi; kk++) {
            int r = kk - kb;
            float4 kv4 = *(const float4*)&sK[r][lane * 4];
            float pa = qa.x * kv4.x + qa.y * kv4.y + qa.z * kv4.z + qa.w * kv4.w;
            float pb = qb.x * kv4.x + qb.y * kv4.y + qb.z * kv4.z + qb.w * kv4.w;
            float s0 = warp_sum(pa);
            float s1 = warp_sum(pb);
            bool v0 = (kk >= kbeg0) && (kk <= q0);
            bool v1 = (kk >= kbeg1);            // kk <= q1 guaranteed by hi
            if (v0 && s0 > m0) {                // warp-uniform branch
                float cr = __expf(m0 - s0);
                l0 *= cr; o0.x *= cr; o0.y *= cr; o0.z *= cr; o0.w *= cr;
                m0 = s0;
            }
            if (v1 && s1 > m1) {
                float cr = __expf(m1 - s1);
                l1 *= cr; o1.x *= cr; o1.y *= cr; o1.z *= cr; o1.w *= cr;
                m1 = s1;
            }
            float p0 = v0 ? __expf(s0 - m0) : 0.f;
            float p1 = v1 ? __expf(s1 - m1) : 0.f;
            l0 += p0; l1 += p1;
            float4 vv = *(const float4*)&sV[r][lane * 4];
            o0.x += p0 * vv.x; o0.y += p0 * vv.y; o0.z += p0 * vv.z; o0.w += p0 * vv.w;
            o1.x += p1 * vv.x; o1.y += p1 * vv.y; o1.z += p1 * vv.z; o1.w += p1 * vv.w;
        }
    }

    float i0 = 1.f / l0;
    float i1 = 1.f / l1;
    float4 r0 = {o0.x * i0, o0.y * i0, o0.z * i0, o0.w * i0};
    float4 r1 = {o1.x * i1, o1.y * i1, o1.z * i1, o1.w * i1};
    *(float4*)&O[((size_t)q0 * NH + h) * HD + lane * 4] = r0;
    *(float4*)&O[((size_t)q1 * NH + h) * HD + lane * 4] = r1;
}

extern "C" void kernel_launch(void* const* d_in, const int* in_sizes, int n_in,
                              void* d_out, int out_size) {
    const float* Q  = (const float*)d_in[0];
    const float* K  = (const float*)d_in[1];
    const float* V  = (const float*)d_in[2];
    const int*   CU = (const int*)d_in[3];
    float* O = (float*)d_out;
    (void)in_sizes; (void)n_in; (void)out_size;

    dim3 grid(NT / BQ, NH);
    attn_fwd<<<grid, 1024>>>(Q, K, V, CU, O);
}

// round 4
// speedup vs baseline: 2.1921x; 2.1921x over previous
#include <cuda_runtime.h>

#define NT 4096      // total tokens
#define NH 16        // query heads
#define NG 4         // kv groups
#define HD 128       // head dim
#define NS 8         // num sequences
#define BQ 64        // queries per block
#define BK 32        // keys per tile
#define NTH 256      // threads per block
#define SQS 132      // sQ row stride (floats, 16B-aligned, bank-staggered)
#define SKS 132      // sK row stride
#define SPS 34       // sP row stride
#define QK_SCALE 0.08838834764831845f  // 1/sqrt(128)

#define SQ_ELEMS (BQ * SQS)   // 8448
#define SK_ELEMS (BK * SKS)   // 4224
#define SV_ELEMS (BK * HD)    // 4096
#define SP_ELEMS (BQ * SPS)   // 2176
#define SMEM_FLOATS (SQ_ELEMS + SK_ELEMS + SV_ELEMS + SP_ELEMS + 3 * BQ)
#define SMEM_BYTES (SMEM_FLOATS * 4 + (NS + 1) * 4)

__global__ __launch_bounds__(NTH, 2)
void attn_fwd(const float* __restrict__ Qg, const float* __restrict__ Kg,
              const float* __restrict__ Vg, const int* __restrict__ CU,
              float* __restrict__ Og)
{
    extern __shared__ float sm[];
    float* sQ  = sm;
    float* sK  = sQ + SQ_ELEMS;
    float* sV  = sK + SK_ELEMS;
    float* sP  = sV + SV_ELEMS;
    float* sM  = sP + SP_ELEMS;
    float* sL  = sM + BQ;
    float* sSc = sL + BQ;
    int*   scu = (int*)(sSc + BQ);

    const int tid = threadIdx.x;
    const int tx  = tid & 15;    // k-col group (QK) / d-col group (PV)
    const int ty  = tid >> 4;    // q-row group (4 rows)
    const int h = blockIdx.y;
    const int g = h >> 2;        // GQA group
    const int q_base = blockIdx.x * BQ;

    if (tid <= NS) scu[tid] = CU[tid];
    if (tid < BQ) { sM[tid] = -1e30f; sL[tid] = 0.f; }

    // Load + pre-scale Q tile (64x128)
    for (int it = tid; it < BQ * HD / 4; it += NTH) {
        int r = it >> 5;
        int c = (it & 31) << 2;
        float4 v = *(const float4*)&Qg[((size_t)(q_base + r) * NH + h) * HD + c];
        v.x *= QK_SCALE; v.y *= QK_SCALE; v.z *= QK_SCALE; v.w *= QK_SCALE;
        *(float4*)&sQ[r * SQS + c] = v;
    }
    __syncthreads();

    // Per-row segment starts
    int kbeg[4];
    int blk_beg = 0;
    {
        const int q0 = q_base + ty * 4;
        #pragma unroll
        for (int i = 0; i < 4; i++) kbeg[i] = 0;
        #pragma unroll
        for (int s = 0; s <= NS; s++) {
            int c = scu[s];
            if (c <= q_base) blk_beg = c;
            #pragma unroll
            for (int i = 0; i < 4; i++) if (c <= q0 + i) kbeg[i] = c;
        }
    }

    float4 o0[4], o1[4];  // output accumulators: 4 q rows x (d=tx*4.., d=64+tx*4..)
    #pragma unroll
    for (int i = 0; i < 4; i++) {
        o0[i] = make_float4(0.f, 0.f, 0.f, 0.f);
        o1[i] = make_float4(0.f, 0.f, 0.f, 0.f);
    }

    const int kv_hi = q_base + BQ - 1;
    for (int kb = blk_beg & ~(BK - 1); kb <= kv_hi; kb += BK) {
        __syncthreads();
        // Stage K/V tiles (rows kb..kb+31, always in-bounds since kb aligned)
        for (int it = tid; it < BK * HD / 4; it += NTH) {
            int r = it >> 5;
            int c = (it & 31) << 2;
            size_t base = ((size_t)(kb + r) * NG + g) * HD + c;
            *(float4*)&sK[r * SKS + c] = *(const float4*)&Kg[base];
            *(float4*)&sV[r * HD  + c] = *(const float4*)&Vg[base];
        }
        __syncthreads();

        // ---- QK^T: 4q x 2k per thread, keys kb+tx and kb+tx+16 ----
        float a0[4] = {0.f, 0.f, 0.f, 0.f};
        float a1[4] = {0.f, 0.f, 0.f, 0.f};
        #pragma unroll 8
        for (int d = 0; d < HD; d += 4) {
            float4 k0 = *(float4*)&sK[tx * SKS + d];
            float4 k1 = *(float4*)&sK[(tx + 16) * SKS + d];
            #pragma unroll
            for (int i = 0; i < 4; i++) {
                float4 q = *(float4*)&sQ[(ty * 4 + i) * SQS + d];
                a0[i] += q.x * k0.x + q.y * k0.y + q.z * k0.z + q.w * k0.w;
                a1[i] += q.x * k1.x + q.y * k1.y + q.z * k1.z + q.w * k1.w;
            }
        }
        #pragma unroll
        for (int i = 0; i < 4; i++) {
            int q   = q_base + ty * 4 + i;
            int k0i = kb + tx;
            int k1i = kb + tx + 16;
            bool v0 = (k0i >= kbeg[i]) && (k0i <= q);
            bool v1 = (k1i >= kbeg[i]) && (k1i <= q);
            sP[(ty * 4 + i) * SPS + tx]      = v0 ? a0[i] : -3.0e38f;
            sP[(ty * 4 + i) * SPS + tx + 16] = v1 ? a1[i] : -3.0e38f;
        }
        __syncthreads();

        // ---- Online softmax, one row per thread (tid < 64) ----
        if (tid < BQ) {
            const int row = tid;
            float m_old = sM[row];
            float mx = m_old;
            #pragma unroll
            for (int c = 0; c < BK; c++) mx = fmaxf(mx, sP[row * SPS + c]);
            float sc = __expf(m_old - mx);
            float sum = 0.f;
            #pragma unroll
            for (int c = 0; c < BK; c++) {
                float p = __expf(sP[row * SPS + c] - mx);
                sum += p;
                sP[row * SPS + c] = p;
            }
            sL[row] = sL[row] * sc + sum;
            sM[row] = mx;
            sSc[row] = sc;
        }
        __syncthreads();

        // ---- Rescale O, then PV: 4q x 8d per thread ----
        #pragma unroll
        for (int i = 0; i < 4; i++) {
            float sc = sSc[ty * 4 + i];
            o0[i].x *= sc; o0[i].y *= sc; o0[i].z *= sc; o0[i].w *= sc;
            o1[i].x *= sc; o1[i].y *= sc; o1[i].z *= sc; o1[i].w *= sc;
        }
        #pragma unroll 4
        for (int k = 0; k < BK; k++) {
            float4 v0 = *(float4*)&sV[k * HD + tx * 4];
            float4 v1 = *(float4*)&sV[k * HD + 64 + tx * 4];
            #pragma unroll
            for (int i = 0; i < 4; i++) {
                float p = sP[(ty * 4 + i) * SPS + k];
                o0[i].x += p * v0.x; o0[i].y += p * v0.y;
                o0[i].z += p * v0.z; o0[i].w += p * v0.w;
                o1[i].x += p * v1.x; o1[i].y += p * v1.y;
                o1[i].z += p * v1.z; o1[i].w += p * v1.w;
            }
        }
    }

    // ---- Epilogue: normalize + store ----
    #pragma unroll
    for (int i = 0; i < 4; i++) {
        int q = q_base + ty * 4 + i;
        float inv = 1.f / sL[ty * 4 + i];
        float4 r0 = o0[i], r1 = o1[i];
        r0.x *= inv; r0.y *= inv; r0.z *= inv; r0.w *= inv;
        r1.x *= inv; r1.y *= inv; r1.z *= inv; r1.w *= inv;
        size_t base = ((size_t)q * NH + h) * HD;
        *(float4*)&Og[base + tx * 4]      = r0;
        *(float4*)&Og[base + 64 + tx * 4] = r1;
    }
}

extern "C" void kernel_launch(void* const* d_in, const int* in_sizes, int n_in,
                              void* d_out, int out_size) {
    const float* Q  = (const float*)d_in[0];
    const float* K  = (const float*)d_in[1];
    const float* V  = (const float*)d_in[2];
    const int*   CU = (const int*)d_in[3];
    float* O = (float*)d_out;
    (void)in_sizes; (void)n_in; (void)out_size;

    cudaFuncSetAttribute(attn_fwd, cudaFuncAttributeMaxDynamicSharedMemorySize, SMEM_BYTES);
    dim3 grid(NT / BQ, NH);
    attn_fwd<<<grid, NTH, SMEM_BYTES>>>(Q, K, V, CU, O);
}